// round 1
// baseline (speedup 1.0000x reference)
#include <cuda_runtime.h>

// GatedDeltaNet chunkwise scan, fp32, one block per (b, h, dv-segment).
// B=2 H=16 S=4096 Dk=128 Dv=256 L=64 -> 64 chunks, 128 blocks of 256 threads.

#define BQ 2
#define HQ 16
#define SQL 4096
#define DKq 128
#define DVq 256
#define LQ 64
#define NCH 64
#define DVSEG 64
#define NSPLIT 4
#define SCL 0.08838834764831845f   // 128^-0.5

// shared strides (floats); all *4 bytes are multiples of 16 for float4
#define QS 132
#define WUS 196
#define AS 68
#define CS 68
#define SS 68

#define SMEM_FLOATS (2*64*QS + 64*WUS + 64*AS + 64*CS + 128*SS + 192)

#define DOT4(a,b) ((a).x*(b).x + (a).y*(b).y + (a).z*(b).z + (a).w*(b).w)
#define UPD4(acc,s,b) { (acc)[0] += (s)*(b).x; (acc)[1] += (s)*(b).y; \
                        (acc)[2] += (s)*(b).z; (acc)[3] += (s)*(b).w; }

__global__ __launch_bounds__(256, 1)
void gdn_kernel(const float* __restrict__ qp, const float* __restrict__ kp,
                const float* __restrict__ vp, const float* __restrict__ gp,
                const float* __restrict__ bp, float* __restrict__ op,
                float* __restrict__ sp)
{
    extern __shared__ float sm[];
    float* sQ  = sm;               // [64][QS]  normalized q
    float* sK  = sQ + 64*QS;       // [64][QS]  normalized k
    float* sWU = sK + 64*QS;       // [64][WUS] W cols 0..127, U cols 128..191
    float* sA  = sWU + 64*WUS;     // [64][AS]  gated kk (then gated qk)
    float* sC  = sA + 64*AS;       // [64][CS]  correction
    float* sS  = sC + 64*CS;       // [128][SS] running state slice
    float* sg  = sS + 128*SS;      // [64] g cumsum
    float* sge = sg + 64;          // [64] exp(g cumsum)
    float* sb  = sge + 64;         // [64] beta

    const int tid = threadIdx.x;
    const int bh  = blockIdx.x >> 2;
    const int seg = blockIdx.x & 3;
    const int tr  = tid >> 4, tc = tid & 15;
    const int w   = tid >> 5, lane = tid & 31;

    const float* qg = qp + (size_t)bh * SQL * DKq;
    const float* kg = kp + (size_t)bh * SQL * DKq;
    const float* vg = vp + (size_t)bh * SQL * DVq + seg * DVSEG;
    const float* gg = gp + (size_t)bh * SQL;
    const float* bg = bp + (size_t)bh * SQL;
    float*       og = op + (size_t)bh * SQL * DVq + seg * DVSEG;

    for (int i = tid; i < 128 * SS; i += 256) sS[i] = 0.f;

    for (int n = 0; n < NCH; n++) {
        __syncthreads();   // protect sQ/sK/sC/sA/sS reuse across chunks

        // ---- load raw q,k + g,beta ----
        const float4* q4 = (const float4*)(qg + (size_t)n * LQ * DKq);
        const float4* k4 = (const float4*)(kg + (size_t)n * LQ * DKq);
        for (int idx = tid; idx < LQ * 32; idx += 256) {
            int r = idx >> 5, c = idx & 31;
            *(float4*)&sQ[r*QS + 4*c] = q4[r*32 + c];
            *(float4*)&sK[r*QS + 4*c] = k4[r*32 + c];
        }
        if (tid < 64) { sg[tid] = gg[n*LQ + tid]; sb[tid] = bg[n*LQ + tid]; }
        __syncthreads();

        // ---- warp 0: inclusive cumsum of g (2 elems/lane) ----
        if (w == 0) {
            float a = sg[2*lane], b = sg[2*lane + 1];
            float s = a + b;
            #pragma unroll
            for (int off = 1; off < 32; off <<= 1) {
                float p = __shfl_up_sync(0xffffffffu, s, off);
                if (lane >= off) s += p;
            }
            float hi = s, lo = s - b;
            sg[2*lane] = lo;  sg[2*lane + 1] = hi;
            sge[2*lane] = __expf(lo); sge[2*lane + 1] = __expf(hi);
        }
        // ---- L2-normalize q,k rows (each warp 8 rows) ----
        for (int r = 8*w; r < 8*w + 8; r++) {
            float aq = 0.f, ak = 0.f;
            #pragma unroll
            for (int c = lane; c < DKq; c += 32) {
                float x = sQ[r*QS + c]; aq += x*x;
                float y = sK[r*QS + c]; ak += y*y;
            }
            #pragma unroll
            for (int off = 16; off; off >>= 1) {
                aq += __shfl_xor_sync(0xffffffffu, aq, off);
                ak += __shfl_xor_sync(0xffffffffu, ak, off);
            }
            float iq = 1.f / (sqrtf(aq) + 1e-6f);
            float ik = 1.f / (sqrtf(ak) + 1e-6f);
            #pragma unroll
            for (int c = lane; c < DKq; c += 32) {
                sQ[r*QS + c] *= iq;
                sK[r*QS + c] *= ik;
            }
        }
        __syncthreads();

        // ---- init RHS: W = beta*gexp*k_norm, U = beta*gexp*v ----
        {
            const float4* v4 = (const float4*)(vg + (size_t)n * LQ * DVq);
            for (int idx = tid; idx < LQ * 16; idx += 256) {
                int r = idx >> 4, c = idx & 15;
                float scl = sb[r] * sge[r];
                float4 vv = v4[r*64 + c];
                vv.x *= scl; vv.y *= scl; vv.z *= scl; vv.w *= scl;
                *(float4*)&sWU[r*WUS + DKq + 4*c] = vv;
            }
            for (int idx = tid; idx < LQ * 32; idx += 256) {
                int r = idx >> 5, c = idx & 31;
                float scl = sb[r] * sge[r];
                float4 kk = *(float4*)&sK[r*QS + 4*c];
                kk.x *= scl; kk.y *= scl; kk.z *= scl; kk.w *= scl;
                *(float4*)&sWU[r*WUS + 4*c] = kk;
            }
        }
        // ---- kk = k k^T, gated -> sA (strictly lower) ----
        {
            float acc[4][4] = {};
            int i0 = 4*tr;
            for (int d = 0; d < DKq; d += 4) {
                float4 aR[4], bR[4];
                #pragma unroll
                for (int ii = 0; ii < 4; ii++) aR[ii] = *(float4*)&sK[(i0+ii)*QS + d];
                #pragma unroll
                for (int jj = 0; jj < 4; jj++) bR[jj] = *(float4*)&sK[(tc+16*jj)*QS + d];
                #pragma unroll
                for (int ii = 0; ii < 4; ii++)
                    #pragma unroll
                    for (int jj = 0; jj < 4; jj++)
                        acc[ii][jj] += DOT4(aR[ii], bR[jj]);
            }
            #pragma unroll
            for (int ii = 0; ii < 4; ii++) {
                int i = i0 + ii; float bi = sb[i], gi = sg[i];
                #pragma unroll
                for (int jj = 0; jj < 4; jj++) {
                    int j = tc + 16*jj;
                    sA[i*AS + j] = (j < i) ? bi * acc[ii][jj] * __expf(sg[j] - gi) : 0.f;
                }
            }
        }
        __syncthreads();

        // ---- forward substitution on [W|U]: row i final, eliminate below ----
        {
            int c4 = tid % 48, rg_ = tid / 48;      // 48 float4 cols, 5 row groups
            for (int i = 0; i < 63; i++) {
                if (tid < 240) {
                    float4 wi = *(float4*)&sWU[i*WUS + 4*c4];
                    for (int r = i + 1 + rg_; r < 64; r += 5) {
                        float a = sA[r*AS + i];
                        float4 wr = *(float4*)&sWU[r*WUS + 4*c4];
                        wr.x -= a*wi.x; wr.y -= a*wi.y; wr.z -= a*wi.z; wr.w -= a*wi.w;
                        *(float4*)&sWU[r*WUS + 4*c4] = wr;
                    }
                }
                __syncthreads();
            }
        }

        // ---- qk^T gated causal * SCALE -> sA (reuse) ----
        {
            float acc[4][4] = {};
            int i0 = 4*tr;
            for (int d = 0; d < DKq; d += 4) {
                float4 aR[4], bR[4];
                #pragma unroll
                for (int ii = 0; ii < 4; ii++) aR[ii] = *(float4*)&sQ[(i0+ii)*QS + d];
                #pragma unroll
                for (int jj = 0; jj < 4; jj++) bR[jj] = *(float4*)&sK[(tc+16*jj)*QS + d];
                #pragma unroll
                for (int ii = 0; ii < 4; ii++)
                    #pragma unroll
                    for (int jj = 0; jj < 4; jj++)
                        acc[ii][jj] += DOT4(aR[ii], bR[jj]);
            }
            #pragma unroll
            for (int ii = 0; ii < 4; ii++) {
                int i = i0 + ii; float gi = sg[i];
                #pragma unroll
                for (int jj = 0; jj < 4; jj++) {
                    int j = tc + 16*jj;
                    sA[i*AS + j] = (j <= i) ? acc[ii][jj] * __expf(sg[j] - gi) * SCL : 0.f;
                }
            }
        }

        // ---- fused: corr = U - W*S  and  accI = q*S (kept in regs) ----
        float accI[4][4] = {};
        {
            float accC[4][4] = {};
            int i0 = 4*tr, c0 = 4*tc;
            for (int d = 0; d < DKq; d += 4) {
                float4 b0 = *(float4*)&sS[(d+0)*SS + c0];
                float4 b1 = *(float4*)&sS[(d+1)*SS + c0];
                float4 b2 = *(float4*)&sS[(d+2)*SS + c0];
                float4 b3 = *(float4*)&sS[(d+3)*SS + c0];
                #pragma unroll
                for (int ii = 0; ii < 4; ii++) {
                    float4 aw = *(float4*)&sWU[(i0+ii)*WUS + d];
                    float4 aq = *(float4*)&sQ[(i0+ii)*QS + d];
                    UPD4(accC[ii], aw.x, b0); UPD4(accC[ii], aw.y, b1);
                    UPD4(accC[ii], aw.z, b2); UPD4(accC[ii], aw.w, b3);
                    UPD4(accI[ii], aq.x, b0); UPD4(accI[ii], aq.y, b1);
                    UPD4(accI[ii], aq.z, b2); UPD4(accI[ii], aq.w, b3);
                }
            }
            #pragma unroll
            for (int ii = 0; ii < 4; ii++) {
                int i = i0 + ii;
                float4 u = *(float4*)&sWU[i*WUS + DKq + c0];
                float4 cc;
                cc.x = u.x - accC[ii][0]; cc.y = u.y - accC[ii][1];
                cc.z = u.z - accC[ii][2]; cc.w = u.w - accC[ii][3];
                *(float4*)&sC[i*CS + c0] = cc;
            }
        }
        __syncthreads();

        // ---- O = accI*gexp*SCALE + qk_gated @ corr ; write out ----
        {
            float accJ[4][4] = {};
            int i0 = 4*tr, c0 = 4*tc;
            for (int j = 0; j < LQ; j += 4) {
                float4 b0 = *(float4*)&sC[(j+0)*CS + c0];
                float4 b1 = *(float4*)&sC[(j+1)*CS + c0];
                float4 b2 = *(float4*)&sC[(j+2)*CS + c0];
                float4 b3 = *(float4*)&sC[(j+3)*CS + c0];
                #pragma unroll
                for (int ii = 0; ii < 4; ii++) {
                    float4 a = *(float4*)&sA[(i0+ii)*AS + j];
                    UPD4(accJ[ii], a.x, b0); UPD4(accJ[ii], a.y, b1);
                    UPD4(accJ[ii], a.z, b2); UPD4(accJ[ii], a.w, b3);
                }
            }
            #pragma unroll
            for (int ii = 0; ii < 4; ii++) {
                int i = i0 + ii; float sc = sge[i] * SCL;
                float4 o;
                o.x = accI[ii][0]*sc + accJ[ii][0];
                o.y = accI[ii][1]*sc + accJ[ii][1];
                o.z = accI[ii][2]*sc + accJ[ii][2];
                o.w = accI[ii][3]*sc + accJ[ii][3];
                *(float4*)&og[((size_t)(n*LQ + i)) * DVq + c0] = o;
            }
        }

        // ---- S = S*exp(g_total) + (gexp.*k)^T @ corr ----
        {
            int d0 = 8*tr, c0 = 4*tc;
            float acc[8][4] = {};
            #pragma unroll 2
            for (int i = 0; i < LQ; i++) {
                float gei = sge[i];
                float4 b = *(float4*)&sC[i*CS + c0];
                #pragma unroll
                for (int r = 0; r < 8; r++) {
                    float a = sK[i*QS + d0 + r] * gei;
                    UPD4(acc[r], a, b);
                }
            }
            float egt = sge[63];
            #pragma unroll
            for (int r = 0; r < 8; r++) {
                float4 s = *(float4*)&sS[(d0+r)*SS + c0];
                s.x = s.x*egt + acc[r][0]; s.y = s.y*egt + acc[r][1];
                s.z = s.z*egt + acc[r][2]; s.w = s.w*egt + acc[r][3];
                *(float4*)&sS[(d0+r)*SS + c0] = s;
            }
        }
    }

    __syncthreads();
    if (sp) {   // final state, if the harness output includes it
        for (int idx = tid; idx < 128 * 16; idx += 256) {
            int d = idx >> 4, c = idx & 15;
            *(float4*)&sp[((size_t)bh*DKq + d) * DVq + seg*DVSEG + 4*c] =
                *(float4*)&sS[d*SS + 4*c];
        }
    }
}

extern "C" void kernel_launch(void* const* d_in, const int* in_sizes, int n_in,
                              void* d_out, int out_size)
{
    const float* q  = (const float*)d_in[0];
    const float* k  = (const float*)d_in[1];
    const float* v  = (const float*)d_in[2];
    const float* g  = (const float*)d_in[3];
    const float* bt = (const float*)d_in[4];
    float* out = (float*)d_out;

    const long long tot_o = (long long)BQ*HQ*SQL*DVq;   // 33,554,432
    const long long tot_s = (long long)BQ*HQ*DKq*DVq;   //  1,048,576
    float* st = ((long long)out_size >= tot_o + tot_s) ? (out + tot_o) : nullptr;

    cudaFuncSetAttribute(gdn_kernel,
                         cudaFuncAttributeMaxDynamicSharedMemorySize,
                         SMEM_FLOATS * sizeof(float));

    gdn_kernel<<<BQ*HQ*NSPLIT, 256, SMEM_FLOATS * sizeof(float)>>>(
        q, k, v, g, bt, out, st);
}

// round 15
// speedup vs baseline: 1.9663x; 1.9663x over previous
#include <cuda_runtime.h>

// GatedDeltaNet chunkwise: two-kernel split.
//  gdn_prep: parallel per (bh,chunk): normalize, cumsum, gated kk/qk, block-4
//            forward substitution for [W|U]. Writes scratch.
//  gdn_scan: sequential per (bh,seg): corr = U - W*S, O, state update.

#define BQ 2
#define HQ 16
#define SQL 4096
#define DKq 128
#define DVq 256
#define LQ 64
#define NCH 64
#define DVSEG 64
#define SCL 0.08838834764831845f   // 128^-0.5

#define QS 132
#define AS 68
#define US 68
#define CS 68
#define SS 68
#define WUS2 388     // 97 float4 columns: W(32) + U(64) + 1 pad
#define NC4 96       // used float4 cols (W 32 + U 64)

// scratch layout per (bh,chunk), in floats
#define SCR_W   0
#define SCR_U   8192
#define SCR_QK  24576
#define SCR_QN  28672
#define SCR_KG  36864
#define SCR_GE  45056
#define SCR_STRIDE 45120

__device__ float g_scr[(size_t)BQ * HQ * NCH * SCR_STRIDE];

#define SMEM_A (2*64*QS + 64*WUS2 + 64*AS + 192)
#define SMEM_B (3*64*QS + 3*64*US + 128*SS + 64)

#define DOT4(a,b) ((a).x*(b).x + (a).y*(b).y + (a).z*(b).z + (a).w*(b).w)
#define UPD4(acc,s,b) { (acc)[0] += (s)*(b).x; (acc)[1] += (s)*(b).y; \
                        (acc)[2] += (s)*(b).z; (acc)[3] += (s)*(b).w; }
// NOTE: parameter names must not collide with float4 member tokens (.x/.y/.z/.w)
#define AXPY4(d_,s_,v_) { (d_).x -= (s_)*(v_).x; (d_).y -= (s_)*(v_).y; \
                          (d_).z -= (s_)*(v_).z; (d_).w -= (s_)*(v_).w; }

// ---------------------------------------------------------------------------
// Kernel A: per-chunk local precompute (fully parallel over 2048 chunks)
// ---------------------------------------------------------------------------
__global__ __launch_bounds__(256, 1)
void gdn_prep(const float* __restrict__ qp, const float* __restrict__ kp,
              const float* __restrict__ vp, const float* __restrict__ gp,
              const float* __restrict__ bp)
{
    extern __shared__ float sm[];
    float* sQ  = sm;                 // [64][QS]
    float* sK  = sQ + 64*QS;         // [64][QS]
    float* sWU = sK + 64*QS;         // [64][WUS2]  W cols 0..127, U cols 128..383
    float* sA  = sWU + 64*WUS2;      // [64][AS]
    float* sg  = sA + 64*AS;
    float* sge = sg + 64;
    float* sb  = sge + 64;

    const int tid = threadIdx.x;
    const int bh  = blockIdx.x >> 6;
    const int n   = blockIdx.x & 63;
    const int tr  = tid >> 4, tc = tid & 15;
    const int w   = tid >> 5, lane = tid & 31;

    const float4* q4 = (const float4*)(qp + ((size_t)bh*SQL + n*LQ) * DKq);
    const float4* k4 = (const float4*)(kp + ((size_t)bh*SQL + n*LQ) * DKq);
    const float4* v4 = (const float4*)(vp + ((size_t)bh*SQL + n*LQ) * DVq);
    const float*  gg = gp + (size_t)bh*SQL + n*LQ;
    const float*  bg = bp + (size_t)bh*SQL + n*LQ;

    // ---- load q,k + g,beta ----
    for (int idx = tid; idx < LQ*32; idx += 256) {
        int r = idx >> 5, c = idx & 31;
        *(float4*)&sQ[r*QS + 4*c] = q4[r*32 + c];
        *(float4*)&sK[r*QS + 4*c] = k4[r*32 + c];
    }
    if (tid < 64) { sg[tid] = gg[tid]; sb[tid] = bg[tid]; }
    __syncthreads();

    // ---- warp 0: inclusive cumsum of g ----
    if (w == 0) {
        float a = sg[2*lane], b = sg[2*lane + 1];
        float s = a + b;
        #pragma unroll
        for (int off = 1; off < 32; off <<= 1) {
            float p = __shfl_up_sync(0xffffffffu, s, off);
            if (lane >= off) s += p;
        }
        float hi = s, lo = s - b;
        sg[2*lane] = lo;  sg[2*lane + 1] = hi;
        sge[2*lane] = __expf(lo); sge[2*lane + 1] = __expf(hi);
    }
    // ---- L2-normalize q,k rows ----
    for (int r = 8*w; r < 8*w + 8; r++) {
        float aq = 0.f, ak = 0.f;
        #pragma unroll
        for (int c = lane; c < DKq; c += 32) {
            float x = sQ[r*QS + c]; aq += x*x;
            float y = sK[r*QS + c]; ak += y*y;
        }
        #pragma unroll
        for (int off = 16; off; off >>= 1) {
            aq += __shfl_xor_sync(0xffffffffu, aq, off);
            ak += __shfl_xor_sync(0xffffffffu, ak, off);
        }
        float iq = 1.f / (sqrtf(aq) + 1e-6f);
        float ik = 1.f / (sqrtf(ak) + 1e-6f);
        #pragma unroll
        for (int c = lane; c < DKq; c += 32) {
            sQ[r*QS + c] *= iq;
            sK[r*QS + c] *= ik;
        }
    }
    __syncthreads();

    // ---- build RHS: [beta*gexp*k_norm | beta*gexp*v] ----
    for (int idx = tid; idx < LQ*64; idx += 256) {
        int r = idx >> 6, c = idx & 63;
        float scl = sb[r] * sge[r];
        float4 vv = v4[r*64 + c];
        vv.x *= scl; vv.y *= scl; vv.z *= scl; vv.w *= scl;
        *(float4*)&sWU[r*WUS2 + DKq + 4*c] = vv;
    }
    for (int idx = tid; idx < LQ*32; idx += 256) {
        int r = idx >> 5, c = idx & 31;
        float scl = sb[r] * sge[r];
        float4 kk = *(float4*)&sK[r*QS + 4*c];
        kk.x *= scl; kk.y *= scl; kk.z *= scl; kk.w *= scl;
        *(float4*)&sWU[r*WUS2 + 4*c] = kk;
    }
    // ---- A = beta_i * kk * gate, strictly lower -> sA ----
    {
        float acc[4][4] = {};
        int i0 = 4*tr;
        for (int d = 0; d < DKq; d += 4) {
            float4 aR[4], bR[4];
            #pragma unroll
            for (int ii = 0; ii < 4; ii++) aR[ii] = *(float4*)&sK[(i0+ii)*QS + d];
            #pragma unroll
            for (int jj = 0; jj < 4; jj++) bR[jj] = *(float4*)&sK[(tc+16*jj)*QS + d];
            #pragma unroll
            for (int ii = 0; ii < 4; ii++)
                #pragma unroll
                for (int jj = 0; jj < 4; jj++)
                    acc[ii][jj] += DOT4(aR[ii], bR[jj]);
        }
        #pragma unroll
        for (int ii = 0; ii < 4; ii++) {
            int i = i0 + ii; float bi = sb[i], gi = sg[i];
            #pragma unroll
            for (int jj = 0; jj < 4; jj++) {
                int j = tc + 16*jj;
                sA[i*AS + j] = (j < i) ? bi * acc[ii][jj] * __expf(sg[j] - gi) : 0.f;
            }
        }
    }
    __syncthreads();

    // ---- blocked forward substitution (unit diagonal), block size 4 ----
    for (int b = 0; b < 16; b++) {
        int i0 = 4*b;
        if (tid < NC4) {                       // 4x4 triangle, column-parallel
            float4 x0 = *(float4*)&sWU[(i0+0)*WUS2 + 4*tid];
            float4 x1 = *(float4*)&sWU[(i0+1)*WUS2 + 4*tid];
            float4 x2 = *(float4*)&sWU[(i0+2)*WUS2 + 4*tid];
            float4 x3 = *(float4*)&sWU[(i0+3)*WUS2 + 4*tid];
            float a10 = sA[(i0+1)*AS + i0];
            float a20 = sA[(i0+2)*AS + i0], a21 = sA[(i0+2)*AS + i0+1];
            float a30 = sA[(i0+3)*AS + i0], a31 = sA[(i0+3)*AS + i0+1],
                  a32 = sA[(i0+3)*AS + i0+2];
            AXPY4(x1, a10, x0);
            AXPY4(x2, a20, x0); AXPY4(x2, a21, x1);
            AXPY4(x3, a30, x0); AXPY4(x3, a31, x1); AXPY4(x3, a32, x2);
            *(float4*)&sWU[(i0+1)*WUS2 + 4*tid] = x1;
            *(float4*)&sWU[(i0+2)*WUS2 + 4*tid] = x2;
            *(float4*)&sWU[(i0+3)*WUS2 + 4*tid] = x3;
        }
        __syncthreads();
        if (b < 15 && tid < 2*NC4) {           // rank-4 update of rows below
            int rg = (tid >= NC4);
            int c4 = tid - (rg ? NC4 : 0);
            float4 w0 = *(float4*)&sWU[(i0+0)*WUS2 + 4*c4];
            float4 w1 = *(float4*)&sWU[(i0+1)*WUS2 + 4*c4];
            float4 w2 = *(float4*)&sWU[(i0+2)*WUS2 + 4*c4];
            float4 w3 = *(float4*)&sWU[(i0+3)*WUS2 + 4*c4];
            for (int r = i0 + 4 + rg; r < 64; r += 2) {
                float4 a = *(float4*)&sA[r*AS + i0];
                float4 wv = *(float4*)&sWU[r*WUS2 + 4*c4];
                AXPY4(wv, a.x, w0); AXPY4(wv, a.y, w1);
                AXPY4(wv, a.z, w2); AXPY4(wv, a.w, w3);
                *(float4*)&sWU[r*WUS2 + 4*c4] = wv;
            }
        }
        __syncthreads();
    }

    // ---- qk gated causal * SCALE -> sA (overwrite) ----
    {
        float acc[4][4] = {};
        int i0 = 4*tr;
        for (int d = 0; d < DKq; d += 4) {
            float4 aR[4], bR[4];
            #pragma unroll
            for (int ii = 0; ii < 4; ii++) aR[ii] = *(float4*)&sQ[(i0+ii)*QS + d];
            #pragma unroll
            for (int jj = 0; jj < 4; jj++) bR[jj] = *(float4*)&sK[(tc+16*jj)*QS + d];
            #pragma unroll
            for (int ii = 0; ii < 4; ii++)
                #pragma unroll
                for (int jj = 0; jj < 4; jj++)
                    acc[ii][jj] += DOT4(aR[ii], bR[jj]);
        }
        #pragma unroll
        for (int ii = 0; ii < 4; ii++) {
            int i = i0 + ii; float gi = sg[i];
            #pragma unroll
            for (int jj = 0; jj < 4; jj++) {
                int j = tc + 16*jj;
                sA[i*AS + j] = (j <= i) ? acc[ii][jj] * __expf(sg[j] - gi) * SCL : 0.f;
            }
        }
    }

    // ---- stores to scratch ----
    size_t base = (size_t)(bh*NCH + n) * SCR_STRIDE;
    float4* scr4 = (float4*)(g_scr + base);
    for (int idx = tid; idx < 2048; idx += 256) {
        int r = idx >> 5, c = idx & 31;
        scr4[SCR_W/4  + idx] = *(float4*)&sWU[r*WUS2 + 4*c];
        scr4[SCR_QN/4 + idx] = *(float4*)&sQ[r*QS + 4*c];
        float4 kk = *(float4*)&sK[r*QS + 4*c];
        float s = sge[r];
        kk.x *= s; kk.y *= s; kk.z *= s; kk.w *= s;
        scr4[SCR_KG/4 + idx] = kk;
    }
    for (int idx = tid; idx < 4096; idx += 256) {
        int r = idx >> 6, c = idx & 63;
        scr4[SCR_U/4 + idx] = *(float4*)&sWU[r*WUS2 + DKq + 4*c];
    }
    if (tid < 64) g_scr[base + SCR_GE + tid] = sge[tid];
    __syncthreads();
    for (int idx = tid; idx < 1024; idx += 256) {
        int r = idx >> 4, c = idx & 15;
        scr4[SCR_QK/4 + idx] = *(float4*)&sA[r*AS + 4*c];
    }
}

// ---------------------------------------------------------------------------
// Kernel B: sequential chunk scan (128 blocks: 32 bh x 4 dv-segments)
// ---------------------------------------------------------------------------
__global__ __launch_bounds__(256, 1)
void gdn_scan(float* __restrict__ op, float* __restrict__ sp)
{
    extern __shared__ float sm[];
    float* sQ  = sm;               // [64][QS] q_norm
    float* sK  = sQ + 64*QS;       // [64][QS] k_gated
    float* sW  = sK + 64*QS;       // [64][QS] solved W
    float* sU  = sW + 64*QS;       // [64][US] solved U (seg)
    float* sA  = sU + 64*US;       // [64][US] gated qk * SCL
    float* sC  = sA + 64*US;       // [64][CS] correction
    float* sS  = sC + 64*CS;       // [128][SS] state slice
    float* sge = sS + 128*SS;      // [64]

    const int tid = threadIdx.x;
    const int bh  = blockIdx.x >> 2;
    const int seg = blockIdx.x & 3;
    const int tr  = tid >> 4, tc = tid & 15;

    float* og = op + (size_t)bh * SQL * DVq + seg * DVSEG;

    for (int i = tid; i < 128 * SS; i += 256) sS[i] = 0.f;

    for (int n = 0; n < NCH; n++) {
        __syncthreads();
        size_t base = (size_t)(bh*NCH + n) * SCR_STRIDE;
        const float4* scr4 = (const float4*)(g_scr + base);
        for (int idx = tid; idx < 2048; idx += 256) {
            int r = idx >> 5, c = idx & 31;
            *(float4*)&sQ[r*QS + 4*c] = scr4[SCR_QN/4 + idx];
            *(float4*)&sK[r*QS + 4*c] = scr4[SCR_KG/4 + idx];
            *(float4*)&sW[r*QS + 4*c] = scr4[SCR_W/4  + idx];
        }
        for (int idx = tid; idx < 1024; idx += 256) {
            int r = idx >> 4, c = idx & 15;
            *(float4*)&sU[r*US + 4*c] = scr4[SCR_U/4  + r*64 + seg*16 + c];
            *(float4*)&sA[r*US + 4*c] = scr4[SCR_QK/4 + r*16 + c];
        }
        if (tid < 64) sge[tid] = g_scr[base + SCR_GE + tid];
        __syncthreads();

        // ---- fused: corr = U - W*S  and  accI = q*S ----
        float accI[4][4] = {};
        {
            float accC[4][4] = {};
            int i0 = 4*tr, c0 = 4*tc;
            for (int d = 0; d < DKq; d += 4) {
                float4 b0 = *(float4*)&sS[(d+0)*SS + c0];
                float4 b1 = *(float4*)&sS[(d+1)*SS + c0];
                float4 b2 = *(float4*)&sS[(d+2)*SS + c0];
                float4 b3 = *(float4*)&sS[(d+3)*SS + c0];
                #pragma unroll
                for (int ii = 0; ii < 4; ii++) {
                    float4 aw = *(float4*)&sW[(i0+ii)*QS + d];
                    float4 aq = *(float4*)&sQ[(i0+ii)*QS + d];
                    UPD4(accC[ii], aw.x, b0); UPD4(accC[ii], aw.y, b1);
                    UPD4(accC[ii], aw.z, b2); UPD4(accC[ii], aw.w, b3);
                    UPD4(accI[ii], aq.x, b0); UPD4(accI[ii], aq.y, b1);
                    UPD4(accI[ii], aq.z, b2); UPD4(accI[ii], aq.w, b3);
                }
            }
            #pragma unroll
            for (int ii = 0; ii < 4; ii++) {
                int i = i0 + ii;
                float4 u = *(float4*)&sU[i*US + c0];
                float4 cc;
                cc.x = u.x - accC[ii][0]; cc.y = u.y - accC[ii][1];
                cc.z = u.z - accC[ii][2]; cc.w = u.w - accC[ii][3];
                *(float4*)&sC[i*CS + c0] = cc;
            }
        }
        __syncthreads();

        // ---- O = accI*gexp*SCL + qk_gated @ corr (lower-tri pruned) ----
        {
            float accJ[4][4] = {};
            int i0 = 4*tr, c0 = 4*tc;
            for (int j = 0; j < i0 + 4; j += 4) {
                float4 b0 = *(float4*)&sC[(j+0)*CS + c0];
                float4 b1 = *(float4*)&sC[(j+1)*CS + c0];
                float4 b2 = *(float4*)&sC[(j+2)*CS + c0];
                float4 b3 = *(float4*)&sC[(j+3)*CS + c0];
                #pragma unroll
                for (int ii = 0; ii < 4; ii++) {
                    float4 a = *(float4*)&sA[(i0+ii)*US + j];
                    UPD4(accJ[ii], a.x, b0); UPD4(accJ[ii], a.y, b1);
                    UPD4(accJ[ii], a.z, b2); UPD4(accJ[ii], a.w, b3);
                }
            }
            #pragma unroll
            for (int ii = 0; ii < 4; ii++) {
                int i = i0 + ii; float sc = sge[i] * SCL;
                float4 o;
                o.x = accI[ii][0]*sc + accJ[ii][0];
                o.y = accI[ii][1]*sc + accJ[ii][1];
                o.z = accI[ii][2]*sc + accJ[ii][2];
                o.w = accI[ii][3]*sc + accJ[ii][3];
                *(float4*)&og[((size_t)(n*LQ + i)) * DVq + c0] = o;
            }
        }

        // ---- S = S*exp(g_total) + k_gated^T @ corr ----
        {
            int d0 = 8*tr, c0 = 4*tc;
            float acc[8][4] = {};
            #pragma unroll 2
            for (int i = 0; i < LQ; i++) {
                float4 b  = *(float4*)&sC[i*CS + c0];
                float4 ka = *(float4*)&sK[i*QS + d0];
                float4 kb = *(float4*)&sK[i*QS + d0 + 4];
                UPD4(acc[0], ka.x, b); UPD4(acc[1], ka.y, b);
                UPD4(acc[2], ka.z, b); UPD4(acc[3], ka.w, b);
                UPD4(acc[4], kb.x, b); UPD4(acc[5], kb.y, b);
                UPD4(acc[6], kb.z, b); UPD4(acc[7], kb.w, b);
            }
            float egt = sge[63];
            #pragma unroll
            for (int r = 0; r < 8; r++) {
                float4 s = *(float4*)&sS[(d0+r)*SS + c0];
                s.x = s.x*egt + acc[r][0]; s.y = s.y*egt + acc[r][1];
                s.z = s.z*egt + acc[r][2]; s.w = s.w*egt + acc[r][3];
                *(float4*)&sS[(d0+r)*SS + c0] = s;
            }
        }
    }

    __syncthreads();
    if (sp) {
        for (int idx = tid; idx < 128 * 16; idx += 256) {
            int d = idx >> 4, c = idx & 15;
            *(float4*)&sp[((size_t)bh*DKq + d) * DVq + seg*DVSEG + 4*c] =
                *(float4*)&sS[d*SS + 4*c];
        }
    }
}

extern "C" void kernel_launch(void* const* d_in, const int* in_sizes, int n_in,
                              void* d_out, int out_size)
{
    const float* q  = (const float*)d_in[0];
    const float* k  = (const float*)d_in[1];
    const float* v  = (const float*)d_in[2];
    const float* g  = (const float*)d_in[3];
    const float* bt = (const float*)d_in[4];
    float* out = (float*)d_out;

    const long long tot_o = (long long)BQ*HQ*SQL*DVq;
    const long long tot_s = (long long)BQ*HQ*DKq*DVq;
    float* st = ((long long)out_size >= tot_o + tot_s) ? (out + tot_o) : nullptr;

    cudaFuncSetAttribute(gdn_prep, cudaFuncAttributeMaxDynamicSharedMemorySize,
                         SMEM_A * sizeof(float));
    cudaFuncSetAttribute(gdn_scan, cudaFuncAttributeMaxDynamicSharedMemorySize,
                         SMEM_B * sizeof(float));

    gdn_prep<<<BQ*HQ*NCH, 256, SMEM_A * sizeof(float)>>>(q, k, v, g, bt);
    gdn_scan<<<BQ*HQ*4, 256, SMEM_B * sizeof(float)>>>(out, st);
}